// round 6
// baseline (speedup 1.0000x reference)
#include <cuda_runtime.h>
#include <cuda_fp16.h>
#include <math.h>
#include <stdint.h>

#define SEQ   512
#define BATCH 64
#define INP   64
#define HID   1024
#define G4    (4 * HID)
#define NBLK  128
#define NTHR  256

// ---- static scratch ----
__device__ float g_xg[(size_t)SEQ * BATCH * G4];   // layout: [jb][t][b][g*8+jl]
__device__ half  g_h_hi[(size_t)SEQ * BATCH * HID];
__device__ half  g_h_lo[(size_t)SEQ * BATCH * HID];
__device__ half  g_w_hi[(size_t)G4 * HID];
__device__ half  g_w_lo[(size_t)G4 * HID];
__device__ half  g_x_hi[(size_t)SEQ * BATCH * INP];
__device__ half  g_x_lo[(size_t)SEQ * BATCH * INP];
__device__ unsigned g_flags[NBLK * 8];
__device__ unsigned g_gen;

// ---- helpers ----
__device__ __forceinline__ void mma16816(float c[4], const uint32_t a[4], const uint32_t b[2]) {
    asm volatile("mma.sync.aligned.m16n8k16.row.col.f32.f16.f16.f32 "
        "{%0,%1,%2,%3}, {%4,%5,%6,%7}, {%8,%9}, {%0,%1,%2,%3};\n"
        : "+f"(c[0]), "+f"(c[1]), "+f"(c[2]), "+f"(c[3])
        : "r"(a[0]), "r"(a[1]), "r"(a[2]), "r"(a[3]), "r"(b[0]), "r"(b[1]));
}
__device__ __forceinline__ void ldsm4(uint32_t r[4], const half* p) {
    uint32_t a = (uint32_t)__cvta_generic_to_shared(p);
    asm volatile("ldmatrix.sync.aligned.m8n8.x4.shared.b16 {%0,%1,%2,%3}, [%4];\n"
        : "=r"(r[0]), "=r"(r[1]), "=r"(r[2]), "=r"(r[3]) : "r"(a));
}
__device__ __forceinline__ void ldsm2(uint32_t r[2], const half* p) {
    uint32_t a = (uint32_t)__cvta_generic_to_shared(p);
    asm volatile("ldmatrix.sync.aligned.m8n8.x2.shared.b16 {%0,%1}, [%2];\n"
        : "=r"(r[0]), "=r"(r[1]) : "r"(a));
}
__device__ __forceinline__ void cp16(void* dst, const void* src) {
    uint32_t d = (uint32_t)__cvta_generic_to_shared(dst);
    asm volatile("cp.async.cg.shared.global [%0], [%1], 16;\n" :: "r"(d), "l"(src));
}
#define CP_COMMIT() asm volatile("cp.async.commit_group;\n")
#define CP_WAIT0()  asm volatile("cp.async.wait_group 0;\n")

__device__ __forceinline__ void cpbulk(void* dst, const void* src, unsigned bytes, void* mbar) {
    uint32_t d = (uint32_t)__cvta_generic_to_shared(dst);
    uint32_t m = (uint32_t)__cvta_generic_to_shared(mbar);
    asm volatile("cp.async.bulk.shared::cta.global.mbarrier::complete_tx::bytes "
                 "[%0], [%1], %2, [%3];\n" :: "r"(d), "l"(src), "r"(bytes), "r"(m) : "memory");
}
__device__ __forceinline__ void mbar_init(void* mbar, unsigned cnt) {
    uint32_t m = (uint32_t)__cvta_generic_to_shared(mbar);
    asm volatile("mbarrier.init.shared.b64 [%0], %1;" :: "r"(m), "r"(cnt) : "memory");
}
__device__ __forceinline__ void mbar_inval(void* mbar) {
    uint32_t m = (uint32_t)__cvta_generic_to_shared(mbar);
    asm volatile("mbarrier.inval.shared.b64 [%0];" :: "r"(m) : "memory");
}
__device__ __forceinline__ void mbar_expect(void* mbar, unsigned bytes) {
    uint32_t m = (uint32_t)__cvta_generic_to_shared(mbar);
    asm volatile("mbarrier.arrive.expect_tx.shared.b64 _, [%0], %1;"
                 :: "r"(m), "r"(bytes) : "memory");
}
__device__ __forceinline__ void mbar_wait(void* mbar, unsigned parity) {
    uint32_t m = (uint32_t)__cvta_generic_to_shared(mbar);
    asm volatile(
        "{\n.reg .pred P;\n"
        "W%=: mbarrier.try_wait.parity.acquire.cta.shared::cta.b64 P, [%0], %1, 0x989680;\n"
        "@P bra D%=;\n"
        "bra W%=;\n"
        "D%=: }\n" :: "r"(m), "r"(parity) : "memory");
}

__device__ __forceinline__ unsigned ld_acq(const unsigned* p) {
    unsigned v;
    asm volatile("ld.acquire.gpu.u32 %0, [%1];" : "=r"(v) : "l"(p) : "memory");
    return v;
}
__device__ __forceinline__ void st_rel(unsigned* p, unsigned v) {
    asm volatile("st.release.gpu.u32 [%0], %1;" :: "l"(p), "r"(v) : "memory");
}
__device__ __forceinline__ float tanh_fast(float x) {
    float y;
    asm("tanh.approx.f32 %0, %1;" : "=f"(y) : "f"(x));
    return y;
}
__device__ __forceinline__ float sigmoid_fast(float x) {
    return 0.5f * tanh_fast(0.5f * x) + 0.5f;
}

__device__ __forceinline__ void grid_barrier(unsigned target) {
    if (blockIdx.x == 0) {
        int tid = threadIdx.x;
        if (tid > 0 && tid < NBLK) {
            while (ld_acq(&g_flags[tid * 8]) < target) { }
        }
        __syncthreads();
        if (tid == 0) st_rel(&g_gen, target);
    } else {
        if (threadIdx.x == 0) {
            __threadfence();
            st_rel(&g_flags[blockIdx.x * 8], target);
            while (ld_acq(&g_gen) < target) { }
        }
        __syncthreads();
    }
}

__global__ void init_bar_kernel() {
    int i = threadIdx.x;
    for (int k = i; k < NBLK * 8; k += 256) g_flags[k] = 0u;
    if (i == 0) g_gen = 0u;
}

__global__ void split_fp16_kernel(const float* __restrict__ src,
                                  half* __restrict__ hi, half* __restrict__ lo, int n) {
    int i4 = (blockIdx.x * 256 + threadIdx.x) * 4;
    if (i4 >= n) return;
    float4 v = *(const float4*)(src + i4);
    half h0 = __float2half(v.x), h1 = __float2half(v.y);
    half h2 = __float2half(v.z), h3 = __float2half(v.w);
    hi[i4+0]=h0; hi[i4+1]=h1; hi[i4+2]=h2; hi[i4+3]=h3;
    lo[i4+0]=__float2half(v.x-__half2float(h0));
    lo[i4+1]=__float2half(v.y-__half2float(h1));
    lo[i4+2]=__float2half(v.z-__half2float(h2));
    lo[i4+3]=__float2half(v.w-__half2float(h3));
}

// ---------------------------------------------------------------------------
// xg[jb][m][g*8+jl] = A[m][K] @ W[4096][K]^T + b1 + b2   (fp16-split, 3-pass)
// ---------------------------------------------------------------------------
__global__ void __launch_bounds__(256)
hgemm_split_kernel(const half* __restrict__ Ahi, const half* __restrict__ Alo,
                   const half* __restrict__ Whi, const half* __restrict__ Wlo,
                   const float* __restrict__ b1, const float* __restrict__ b2,
                   float* __restrict__ C, int M, int K) {
    __shared__ half sA[2][2][64 * 40];
    __shared__ half sB[2][2][64 * 40];
    const int tid = threadIdx.x, lane = tid & 31, w = tid >> 5;
    const int mi = w & 1, ni = w >> 1;
    const int r = lane >> 2, q = lane & 3;
    const int m0 = blockIdx.y * 64, n0 = blockIdx.x * 64;
    const int srow = tid >> 2, skq = (tid & 3) * 8;

    float acc[2][2][4];
#pragma unroll
    for (int a = 0; a < 2; a++)
#pragma unroll
        for (int b = 0; b < 2; b++)
#pragma unroll
            for (int c = 0; c < 4; c++) acc[a][b][c] = 0.f;

    const int NIT = K / 32;
    cp16(&sA[0][0][srow*40+skq], Ahi + (size_t)(m0+srow)*K + skq);
    cp16(&sA[0][1][srow*40+skq], Alo + (size_t)(m0+srow)*K + skq);
    cp16(&sB[0][0][srow*40+skq], Whi + (size_t)(n0+srow)*K + skq);
    cp16(&sB[0][1][srow*40+skq], Wlo + (size_t)(n0+srow)*K + skq);
    CP_COMMIT();

    for (int it = 0; it < NIT; it++) {
        CP_WAIT0();
        __syncthreads();
        if (it + 1 < NIT) {
            int k0 = (it+1)*32, bf = (it+1) & 1;
            cp16(&sA[bf][0][srow*40+skq], Ahi + (size_t)(m0+srow)*K + k0 + skq);
            cp16(&sA[bf][1][srow*40+skq], Alo + (size_t)(m0+srow)*K + k0 + skq);
            cp16(&sB[bf][0][srow*40+skq], Whi + (size_t)(n0+srow)*K + k0 + skq);
            cp16(&sB[bf][1][srow*40+skq], Wlo + (size_t)(n0+srow)*K + k0 + skq);
            CP_COMMIT();
        }
        const half *Abh = sA[it&1][0], *Abl = sA[it&1][1];
        const half *Bbh = sB[it&1][0], *Bbl = sB[it&1][1];
#pragma unroll
        for (int s = 0; s < 2; s++) {
            const int kb = s * 16;
            uint32_t Ah[2][4], Al[2][4], Bh[2][2], Bl[2][2];
#pragma unroll
            for (int mt = 0; mt < 2; mt++) {
                ldsm4(Ah[mt], Abh + (mi*32 + mt*16 + (lane&15))*40 + kb + ((lane>>4)<<3));
                ldsm4(Al[mt], Abl + (mi*32 + mt*16 + (lane&15))*40 + kb + ((lane>>4)<<3));
            }
#pragma unroll
            for (int nt = 0; nt < 2; nt++) {
                ldsm2(Bh[nt], Bbh + (ni*16 + nt*8 + (lane&7))*40 + kb + (((lane>>3)&1)<<3));
                ldsm2(Bl[nt], Bbl + (ni*16 + nt*8 + (lane&7))*40 + kb + (((lane>>3)&1)<<3));
            }
#pragma unroll
            for (int mt = 0; mt < 2; mt++)
#pragma unroll
                for (int nt = 0; nt < 2; nt++) {
                    mma16816(acc[mt][nt], Ah[mt], Bh[nt]);
                    mma16816(acc[mt][nt], Ah[mt], Bl[nt]);
                    mma16816(acc[mt][nt], Al[mt], Bh[nt]);
                }
        }
        __syncthreads();
    }
    // epilogue: scatter into [jb][m][g*8+jl]
#pragma unroll
    for (int mt = 0; mt < 2; mt++)
#pragma unroll
        for (int nt = 0; nt < 2; nt++) {
            int row = m0 + mi*32 + mt*16 + r;
            int col = n0 + ni*16 + nt*8 + q*2;
            int g = col >> 10, rem = col & 1023, jb = rem >> 3, jl = rem & 7;
            float bs0 = b1[col] + b2[col], bs1 = b1[col+1] + b2[col+1];
            size_t base = (size_t)jb * ((size_t)SEQ * BATCH * 32) + (size_t)row * 32 + g*8 + jl;
            *(float2*)(C + base) = make_float2(acc[mt][nt][0]+bs0, acc[mt][nt][1]+bs1);
            *(float2*)(C + base + 8*32) = make_float2(acc[mt][nt][2]+bs0, acc[mt][nt][3]+bs1);
        }
}

// ---------------------------------------------------------------------------
// Persistent mma LSTM layer with bulk-copy staging.
// ---------------------------------------------------------------------------
#define WSS 1032
#define HSS 136
#define WS_PART_B (32 * WSS * 2)
#define HS_PART_B (64 * HSS * 2)
#define HS_OFF    (2 * WS_PART_B)            // 132096
#define PS_OFF    (HS_OFF + 4 * HS_PART_B)   // 201728
#define XG_OFF    (PS_OFF + 64 * 34 * 4)     // 210432
#define MB_OFF    (XG_OFF + 2 * 8192)        // 226816
#define SMEM_TOT  (MB_OFF + 64)              // 226880
#define CHUNK_B   32768u                     // 2 parts x 64 rows x 256 B
#define XG_B      8192u

__global__ void __launch_bounds__(NTHR, 1)
lstm_layer_mma(const float* __restrict__ xg,     // [jb][SEQ*B][32] incl. biases
               const float* __restrict__ Whh,    // [4H][H] fp32
               half* __restrict__ hhi, half* __restrict__ hlo,  // [SEQ][B][H]
               float* __restrict__ hseq)         // fp32 out or null
{
    extern __shared__ char smem[];
    half*  wsh  = (half*)smem;
    half*  wsl  = (half*)(smem + WS_PART_B);
    float* psum = (float*)(smem + PS_OFF);
    float* xgs  = (float*)(smem + XG_OFF);
    uint64_t* hmb  = (uint64_t*)(smem + MB_OFF);       // [2]
    uint64_t* xmb  = (uint64_t*)(smem + MB_OFF + 16);  // [2]

    const int tid = threadIdx.x, lane = tid & 31, w = tid >> 5;
    const int mi = w & 1, ni = w >> 1;
    const int r = lane >> 2, q = lane & 3;
    const int j0 = blockIdx.x * 8;
    const float* xgb = xg + (size_t)blockIdx.x * ((size_t)SEQ * BATCH * 32);

    if (tid == 0) {
        mbar_init(&hmb[0], 1); mbar_init(&hmb[1], 1);
        mbar_init(&xmb[0], 1); mbar_init(&xmb[1], 1);
    }

    // one-time: load + split Whh slice into smem (rows n = g*8+jl)
    for (int idx = tid; idx < 32 * 256; idx += NTHR) {
        int n = idx >> 8, kq = (idx & 255) * 4;
        int grow = (n >> 3) * HID + j0 + (n & 7);
        float4 v = *(const float4*)(Whh + (size_t)grow * HID + kq);
        half h0=__float2half(v.x), h1=__float2half(v.y), h2=__float2half(v.z), h3=__float2half(v.w);
        half* ph = wsh + n * WSS + kq;
        half* pl = wsl + n * WSS + kq;
        ph[0]=h0; ph[1]=h1; ph[2]=h2; ph[3]=h3;
        pl[0]=__float2half(v.x-__half2float(h0));
        pl[1]=__float2half(v.y-__half2float(h1));
        pl[2]=__float2half(v.z-__half2float(h2));
        pl[3]=__float2half(v.w-__half2float(h3));
    }
    __syncthreads();   // mbar init + weights visible

    // prologue: xg(0)
    if (tid == 0) {
        mbar_expect(&xmb[0], XG_B);
        cpbulk(xgs, xgb, XG_B, &xmb[0]);
    }

    unsigned hph[2] = {0u, 0u};
    unsigned xph[2] = {0u, 0u};
    float creg[2] = {0.f, 0.f};

    for (int t = 0; t < SEQ; t++) {
        float acc[2][4];
#pragma unroll
        for (int a = 0; a < 2; a++)
#pragma unroll
            for (int c = 0; c < 4; c++) acc[a][c] = 0.f;

        // step prologue: expects, then issue chunk0 (t>0) + xg(t+1)
        if (tid == 0) {
            if (t > 0) mbar_expect(&hmb[0], CHUNK_B);
            if (t + 1 < SEQ) mbar_expect(&xmb[(t+1)&1], XG_B);
        }
        __syncthreads();

        const half* srcH = hhi + (size_t)(t-1) * BATCH * HID;
        const half* srcL = hlo + (size_t)(t-1) * BATCH * HID;

        if (t > 0 && tid < 128) {
            int part = tid >> 6, row = tid & 63;
            const half* src = (part ? srcL : srcH) + (size_t)row * HID;
            half* dst = (half*)(smem + HS_OFF + part * HS_PART_B) + row * HSS;
            cpbulk(dst, src, 256u, &hmb[0]);
        }
        if (tid == 128 && t + 1 < SEQ) {
            cpbulk(xgs + ((t+1)&1) * 2048, xgb + (size_t)(t+1) * 2048, XG_B, &xmb[(t+1)&1]);
        }

        if (t > 0) {
            for (int c = 0; c < 8; c++) {
                if (c + 1 < 8 && tid == 0) mbar_expect(&hmb[(c+1)&1], CHUNK_B);
                mbar_wait(&hmb[c&1], hph[c&1]); hph[c&1] ^= 1u;
                __syncthreads();
                if (c + 1 < 8 && tid < 128) {
                    int part = tid >> 6, row = tid & 63;
                    const half* src = (part ? srcL : srcH) + (size_t)row * HID + (c+1) * 128;
                    half* dst = (half*)(smem + HS_OFF + (((c+1)&1)*2 + part) * HS_PART_B) + row * HSS;
                    cpbulk(dst, src, 256u, &hmb[(c+1)&1]);
                }
                const half* hh = (half*)(smem + HS_OFF + ((c&1)*2+0)*HS_PART_B);
                const half* hl = (half*)(smem + HS_OFF + ((c&1)*2+1)*HS_PART_B);
#pragma unroll
                for (int s = 0; s < 8; s++) {
                    const int kb = s * 16, kg = c * 128 + kb;
                    uint32_t Ah[2][4], Al[2][4], Bh[2], Bl[2];
#pragma unroll
                    for (int mt = 0; mt < 2; mt++) {
                        ldsm4(Ah[mt], hh + (mi*32 + mt*16 + (lane&15))*HSS + kb + ((lane>>4)<<3));
                        ldsm4(Al[mt], hl + (mi*32 + mt*16 + (lane&15))*HSS + kb + ((lane>>4)<<3));
                    }
                    ldsm2(Bh, wsh + (ni*8 + (lane&7))*WSS + kg + (((lane>>3)&1)<<3));
                    ldsm2(Bl, wsl + (ni*8 + (lane&7))*WSS + kg + (((lane>>3)&1)<<3));
#pragma unroll
                    for (int mt = 0; mt < 2; mt++) {
                        mma16816(acc[mt], Ah[mt], Bh);
                        mma16816(acc[mt], Ah[mt], Bl);
                        mma16816(acc[mt], Al[mt], Bh);
                    }
                }
            }
            __syncthreads();   // last chunk compute done before psum overwrite

#pragma unroll
            for (int mt = 0; mt < 2; mt++) {
                int row = mi*32 + mt*16 + r, col = ni*8 + q*2;
                *(float2*)(psum + row*34 + col) = make_float2(acc[mt][0], acc[mt][1]);
                *(float2*)(psum + (row+8)*34 + col) = make_float2(acc[mt][2], acc[mt][3]);
            }
            __syncthreads();
        }

        // pointwise cell update
        mbar_wait(&xmb[t&1], xph[t&1]); xph[t&1] ^= 1u;
        const float* xt = xgs + (t&1) * 2048;
        float* h_out = hseq ? hseq + (size_t)t * BATCH * HID : (float*)0;
        half* hhio = hhi + (size_t)t * BATCH * HID;
        half* hloo = hlo + (size_t)t * BATCH * HID;
#pragma unroll
        for (int qq = 0; qq < 2; qq++) {
            int p = tid + NTHR * qq;
            int b = p >> 3, jl = p & 7, j = j0 + jl;
            const float* xr = xt + b * 32 + jl;
            float ig = xr[0], fg = xr[8], gg = xr[16], og = xr[24];
            if (t > 0) {
                ig += psum[b*34 + jl];
                fg += psum[b*34 + 8 + jl];
                gg += psum[b*34 + 16 + jl];
                og += psum[b*34 + 24 + jl];
            }
            ig = sigmoid_fast(ig);
            fg = sigmoid_fast(fg);
            gg = tanh_fast(gg);
            og = sigmoid_fast(og);
            float cn = fg * creg[qq] + ig * gg;
            creg[qq] = cn;
            float hv = og * tanh_fast(cn);
            size_t idx = (size_t)b * HID + j;
            if (h_out) h_out[idx] = hv;
            half hh = __float2half(hv);
            hhio[idx] = hh;
            hloo[idx] = __float2half(hv - __half2float(hh));
        }
        grid_barrier((unsigned)(t + 1));
    }

    __syncthreads();
    if (tid == 0) {
        mbar_inval(&hmb[0]); mbar_inval(&hmb[1]);
        mbar_inval(&xmb[0]); mbar_inval(&xmb[1]);
    }
}

// ---------------------------------------------------------------------------
__global__ void final_linear_kernel(const float* __restrict__ h_last,
                                    const float* __restrict__ Wl,
                                    const float* __restrict__ bl,
                                    float* __restrict__ y) {
    int b = blockIdx.x;
    __shared__ float red[128];
    float s = 0.f;
    for (int k = threadIdx.x; k < HID; k += 128)
        s += h_last[(size_t)b * HID + k] * Wl[k];
    red[threadIdx.x] = s;
    __syncthreads();
    for (int off = 64; off > 0; off >>= 1) {
        if (threadIdx.x < off) red[threadIdx.x] += red[threadIdx.x + off];
        __syncthreads();
    }
    if (threadIdx.x == 0) y[b] = red[0] + bl[0];
}

// ---------------------------------------------------------------------------
extern "C" void kernel_launch(void* const* d_in, const int* in_sizes, int n_in,
                              void* d_out, int out_size) {
    (void)in_sizes; (void)n_in; (void)out_size;
    const float* x    = (const float*)d_in[0];
    const float* Wih0 = (const float*)d_in[1];
    const float* Whh0 = (const float*)d_in[2];
    const float* bih0 = (const float*)d_in[3];
    const float* bhh0 = (const float*)d_in[4];
    const float* Wih1 = (const float*)d_in[5];
    const float* Whh1 = (const float*)d_in[6];
    const float* bih1 = (const float*)d_in[7];
    const float* bhh1 = (const float*)d_in[8];
    const float* Wlin = (const float*)d_in[9];
    const float* blin = (const float*)d_in[10];

    float* out      = (float*)d_out;
    float* lstm_out = out;
    float* ypred    = out + (size_t)SEQ * BATCH * HID;

    float *xg; half *hhi, *hlo, *whi, *wlo, *xhi, *xlo;
    cudaGetSymbolAddress((void**)&xg,  g_xg);
    cudaGetSymbolAddress((void**)&hhi, g_h_hi);
    cudaGetSymbolAddress((void**)&hlo, g_h_lo);
    cudaGetSymbolAddress((void**)&whi, g_w_hi);
    cudaGetSymbolAddress((void**)&wlo, g_w_lo);
    cudaGetSymbolAddress((void**)&xhi, g_x_hi);
    cudaGetSymbolAddress((void**)&xlo, g_x_lo);

    cudaFuncSetAttribute(lstm_layer_mma,
                         cudaFuncAttributeMaxDynamicSharedMemorySize, SMEM_TOT);

    const int M = SEQ * BATCH;
    dim3 gg(G4 / 64, M / 64);

    // Layer 0
    int nx = SEQ * BATCH * INP;
    split_fp16_kernel<<<nx/4/256, 256>>>(x, xhi, xlo, nx);
    int nw0 = G4 * INP;
    split_fp16_kernel<<<nw0/4/256, 256>>>(Wih0, whi, wlo, nw0);
    hgemm_split_kernel<<<gg, 256>>>(xhi, xlo, whi, wlo, bih0, bhh0, xg, M, INP);
    init_bar_kernel<<<1, 256>>>();
    lstm_layer_mma<<<NBLK, NTHR, SMEM_TOT>>>(xg, Whh0, hhi, hlo, (float*)0);

    // Layer 1
    int nw1 = G4 * HID;
    split_fp16_kernel<<<nw1/4/256, 256>>>(Wih1, whi, wlo, nw1);
    hgemm_split_kernel<<<gg, 256>>>(hhi, hlo, whi, wlo, bih1, bhh1, xg, M, HID);
    init_bar_kernel<<<1, 256>>>();
    lstm_layer_mma<<<NBLK, NTHR, SMEM_TOT>>>(xg, Whh1, hhi, hlo, lstm_out);

    // Head
    final_linear_kernel<<<BATCH, 128>>>(lstm_out + (size_t)(SEQ-1) * BATCH * HID,
                                        Wlin, blin, ypred);
}

// round 7
// speedup vs baseline: 1.3317x; 1.3317x over previous
#include <cuda_runtime.h>
#include <cuda_fp16.h>
#include <math.h>
#include <stdint.h>

#define SEQ   512
#define BATCH 64
#define INP   64
#define HID   1024
#define G4    (4 * HID)
#define NBLK  128
#define NTHR  256

// ---- static scratch ----
__device__ float g_xg[(size_t)SEQ * BATCH * G4];   // [jb][t*64+b][32]
__device__ half  g_h_hi[(size_t)SEQ * BATCH * HID]; // chunked-swizzled layout
__device__ half  g_h_lo[(size_t)SEQ * BATCH * HID];
__device__ half  g_w_hi[(size_t)G4 * HID];
__device__ half  g_w_lo[(size_t)G4 * HID];
__device__ half  g_x_hi[(size_t)SEQ * BATCH * INP];
__device__ half  g_x_lo[(size_t)SEQ * BATCH * INP];
__device__ unsigned g_flags[NBLK * 8];   // zero-init; self-resetting
__device__ unsigned g_gen;

// ---- helpers ----
__device__ __forceinline__ void mma16816(float c[4], const uint32_t a[4], const uint32_t b[2]) {
    asm volatile("mma.sync.aligned.m16n8k16.row.col.f32.f16.f16.f32 "
        "{%0,%1,%2,%3}, {%4,%5,%6,%7}, {%8,%9}, {%0,%1,%2,%3};\n"
        : "+f"(c[0]), "+f"(c[1]), "+f"(c[2]), "+f"(c[3])
        : "r"(a[0]), "r"(a[1]), "r"(a[2]), "r"(a[3]), "r"(b[0]), "r"(b[1]));
}
__device__ __forceinline__ void ldsm4(uint32_t r[4], const half* p) {
    uint32_t a = (uint32_t)__cvta_generic_to_shared(p);
    asm volatile("ldmatrix.sync.aligned.m8n8.x4.shared.b16 {%0,%1,%2,%3}, [%4];\n"
        : "=r"(r[0]), "=r"(r[1]), "=r"(r[2]), "=r"(r[3]) : "r"(a));
}
__device__ __forceinline__ void ldsm2(uint32_t r[2], const half* p) {
    uint32_t a = (uint32_t)__cvta_generic_to_shared(p);
    asm volatile("ldmatrix.sync.aligned.m8n8.x2.shared.b16 {%0,%1}, [%2];\n"
        : "=r"(r[0]), "=r"(r[1]) : "r"(a));
}
__device__ __forceinline__ void cp16(void* dst, const void* src) {
    uint32_t d = (uint32_t)__cvta_generic_to_shared(dst);
    asm volatile("cp.async.cg.shared.global [%0], [%1], 16;\n" :: "r"(d), "l"(src));
}
#define CP_COMMIT() asm volatile("cp.async.commit_group;\n")
#define CP_WAIT0()  asm volatile("cp.async.wait_group 0;\n")

__device__ __forceinline__ void cpbulk(void* dst, const void* src, unsigned bytes, void* mbar) {
    uint32_t d = (uint32_t)__cvta_generic_to_shared(dst);
    uint32_t m = (uint32_t)__cvta_generic_to_shared(mbar);
    asm volatile("cp.async.bulk.shared::cta.global.mbarrier::complete_tx::bytes "
                 "[%0], [%1], %2, [%3];\n" :: "r"(d), "l"(src), "r"(bytes), "r"(m) : "memory");
}
__device__ __forceinline__ void mbar_init(void* mbar, unsigned cnt) {
    uint32_t m = (uint32_t)__cvta_generic_to_shared(mbar);
    asm volatile("mbarrier.init.shared.b64 [%0], %1;" :: "r"(m), "r"(cnt) : "memory");
}
__device__ __forceinline__ void mbar_inval(void* mbar) {
    uint32_t m = (uint32_t)__cvta_generic_to_shared(mbar);
    asm volatile("mbarrier.inval.shared.b64 [%0];" :: "r"(m) : "memory");
}
__device__ __forceinline__ void mbar_expect(void* mbar, unsigned bytes) {
    uint32_t m = (uint32_t)__cvta_generic_to_shared(mbar);
    asm volatile("mbarrier.arrive.expect_tx.shared.b64 _, [%0], %1;"
                 :: "r"(m), "r"(bytes) : "memory");
}
__device__ __forceinline__ void mbar_wait(void* mbar, unsigned parity) {
    uint32_t m = (uint32_t)__cvta_generic_to_shared(mbar);
    asm volatile(
        "{\n.reg .pred P;\n"
        "W%=: mbarrier.try_wait.parity.acquire.cta.shared::cta.b64 P, [%0], %1, 0x989680;\n"
        "@P bra D%=;\n"
        "bra W%=;\n"
        "D%=: }\n" :: "r"(m), "r"(parity) : "memory");
}
__device__ __forceinline__ unsigned ld_acq(const unsigned* p) {
    unsigned v;
    asm volatile("ld.acquire.gpu.u32 %0, [%1];" : "=r"(v) : "l"(p) : "memory");
    return v;
}
__device__ __forceinline__ void st_rel(unsigned* p, unsigned v) {
    asm volatile("st.release.gpu.u32 [%0], %1;" :: "l"(p), "r"(v) : "memory");
}
__device__ __forceinline__ float tanh_fast(float x) {
    float y;
    asm("tanh.approx.f32 %0, %1;" : "=f"(y) : "f"(x));
    return y;
}
__device__ __forceinline__ float sigmoid_fast(float x) {
    return 0.5f * tanh_fast(0.5f * x) + 0.5f;
}

// Grid barrier: writes released after a block-wide sync; monotonic targets.
__device__ __forceinline__ void grid_barrier(unsigned target) {
    __syncthreads();   // all threads' writes happen-before the release below
    int tid = threadIdx.x;
    if (blockIdx.x == 0) {
        if (tid > 0 && tid < NBLK) {
            while (ld_acq(&g_flags[tid * 8]) < target) { }
        }
        __syncthreads();
        if (tid == 0) st_rel(&g_gen, target);
    } else {
        if (tid == 0) {
            st_rel(&g_flags[blockIdx.x * 8], target);
            while (ld_acq(&g_gen) < target) { }
        }
        __syncthreads();
    }
}

__global__ void split_fp16_kernel(const float* __restrict__ src,
                                  half* __restrict__ hi, half* __restrict__ lo, int n) {
    int i4 = (blockIdx.x * 256 + threadIdx.x) * 4;
    if (i4 >= n) return;
    float4 v = *(const float4*)(src + i4);
    half h0 = __float2half(v.x), h1 = __float2half(v.y);
    half h2 = __float2half(v.z), h3 = __float2half(v.w);
    hi[i4+0]=h0; hi[i4+1]=h1; hi[i4+2]=h2; hi[i4+3]=h3;
    lo[i4+0]=__float2half(v.x-__half2float(h0));
    lo[i4+1]=__float2half(v.y-__half2float(h1));
    lo[i4+2]=__float2half(v.z-__half2float(h2));
    lo[i4+3]=__float2half(v.w-__half2float(h3));
}

// Address of logical A[m][k] when A is in the chunked-swizzled h layout.
__device__ __forceinline__ const half* h_addr(const half* A, int m, int k) {
    int b = m & 63, t = m >> 6;
    int c = k >> 7, sl = (k >> 3) & 15, sp = sl ^ (b & 7);
    return A + (size_t)t * 65536 + ((size_t)c * 64 + b) * 128 + sp * 8;
}

// ---------------------------------------------------------------------------
// xg[jb][m][g*8+jl] = A[m][K] @ W[4096][K]^T + b1 + b2   (fp16-split, 3-pass)
// achunked: A stored in chunked-swizzled h layout (layer 1).
// ---------------------------------------------------------------------------
__global__ void __launch_bounds__(256)
hgemm_split_kernel(const half* __restrict__ Ahi, const half* __restrict__ Alo,
                   const half* __restrict__ Whi, const half* __restrict__ Wlo,
                   const float* __restrict__ b1, const float* __restrict__ b2,
                   float* __restrict__ C, int M, int K, int achunked) {
    __shared__ half sA[2][2][64 * 40];
    __shared__ half sB[2][2][64 * 40];
    const int tid = threadIdx.x, lane = tid & 31, w = tid >> 5;
    const int mi = w & 1, ni = w >> 1;
    const int r = lane >> 2, q = lane & 3;
    const int m0 = blockIdx.y * 64, n0 = blockIdx.x * 64;
    const int srow = tid >> 2, skq = (tid & 3) * 8;

    float acc[2][2][4];
#pragma unroll
    for (int a = 0; a < 2; a++)
#pragma unroll
        for (int b = 0; b < 2; b++)
#pragma unroll
            for (int c = 0; c < 4; c++) acc[a][b][c] = 0.f;

    const int NIT = K / 32;
    {
        const half* ah = achunked ? h_addr(Ahi, m0+srow, skq) : Ahi + (size_t)(m0+srow)*K + skq;
        const half* al = achunked ? h_addr(Alo, m0+srow, skq) : Alo + (size_t)(m0+srow)*K + skq;
        cp16(&sA[0][0][srow*40+skq], ah);
        cp16(&sA[0][1][srow*40+skq], al);
        cp16(&sB[0][0][srow*40+skq], Whi + (size_t)(n0+srow)*K + skq);
        cp16(&sB[0][1][srow*40+skq], Wlo + (size_t)(n0+srow)*K + skq);
        CP_COMMIT();
    }

    for (int it = 0; it < NIT; it++) {
        CP_WAIT0();
        __syncthreads();
        if (it + 1 < NIT) {
            int k0 = (it+1)*32, bf = (it+1) & 1;
            const half* ah = achunked ? h_addr(Ahi, m0+srow, k0+skq) : Ahi + (size_t)(m0+srow)*K + k0 + skq;
            const half* al = achunked ? h_addr(Alo, m0+srow, k0+skq) : Alo + (size_t)(m0+srow)*K + k0 + skq;
            cp16(&sA[bf][0][srow*40+skq], ah);
            cp16(&sA[bf][1][srow*40+skq], al);
            cp16(&sB[bf][0][srow*40+skq], Whi + (size_t)(n0+srow)*K + k0 + skq);
            cp16(&sB[bf][1][srow*40+skq], Wlo + (size_t)(n0+srow)*K + k0 + skq);
            CP_COMMIT();
        }
        const half *Abh = sA[it&1][0], *Abl = sA[it&1][1];
        const half *Bbh = sB[it&1][0], *Bbl = sB[it&1][1];
#pragma unroll
        for (int s = 0; s < 2; s++) {
            const int kb = s * 16;
            uint32_t Ah[2][4], Al[2][4], Bh[2][2], Bl[2][2];
#pragma unroll
            for (int mt = 0; mt < 2; mt++) {
                ldsm4(Ah[mt], Abh + (mi*32 + mt*16 + (lane&15))*40 + kb + ((lane>>4)<<3));
                ldsm4(Al[mt], Abl + (mi*32 + mt*16 + (lane&15))*40 + kb + ((lane>>4)<<3));
            }
#pragma unroll
            for (int nt = 0; nt < 2; nt++) {
                ldsm2(Bh[nt], Bbh + (ni*16 + nt*8 + (lane&7))*40 + kb + (((lane>>3)&1)<<3));
                ldsm2(Bl[nt], Bbl + (ni*16 + nt*8 + (lane&7))*40 + kb + (((lane>>3)&1)<<3));
            }
#pragma unroll
            for (int mt = 0; mt < 2; mt++)
#pragma unroll
                for (int nt = 0; nt < 2; nt++) {
                    mma16816(acc[mt][nt], Ah[mt], Bh[nt]);
                    mma16816(acc[mt][nt], Ah[mt], Bl[nt]);
                    mma16816(acc[mt][nt], Al[mt], Bh[nt]);
                }
        }
        __syncthreads();
    }
#pragma unroll
    for (int mt = 0; mt < 2; mt++)
#pragma unroll
        for (int nt = 0; nt < 2; nt++) {
            int row = m0 + mi*32 + mt*16 + r;
            int col = n0 + ni*16 + nt*8 + q*2;
            int g = col >> 10, rem = col & 1023, jb = rem >> 3, jl = rem & 7;
            float bs0 = b1[col] + b2[col], bs1 = b1[col+1] + b2[col+1];
            size_t base = (size_t)jb * ((size_t)SEQ * BATCH * 32) + (size_t)row * 32 + g*8 + jl;
            *(float2*)(C + base) = make_float2(acc[mt][nt][0]+bs0, acc[mt][nt][1]+bs1);
            *(float2*)(C + base + 8*32) = make_float2(acc[mt][nt][2]+bs0, acc[mt][nt][3]+bs1);
        }
}

// ---------------------------------------------------------------------------
// Persistent mma LSTM layer; h staged by 16KB bulk copies (2 per chunk).
// smem: W hi/lo 132096 | h 2buf x 32KB 65536 | psum 8704 | hsm 2048 |
//       xg 2x8192 | mbar 64   = 224832
// ---------------------------------------------------------------------------
#define WSS 1032
#define WS_PART_B (32 * WSS * 2)          // 66048
#define HS_OFF    (2 * WS_PART_B)         // 132096
#define PS_OFF    (HS_OFF + 65536)        // 197632
#define HSM_OFF   (PS_OFF + 8704)         // 206336
#define XG_OFF    (HSM_OFF + 2048)        // 208384
#define MB_OFF    (XG_OFF + 16384)        // 224768
#define SMEM_TOT  (MB_OFF + 64)           // 224832
#define XG_B      8192u

__global__ void __launch_bounds__(NTHR, 1)
lstm_layer_mma(const float* __restrict__ xg,     // [jb][t*64+b][32] incl. biases
               const float* __restrict__ Whh,    // [4H][H] fp32
               half* __restrict__ hhi, half* __restrict__ hlo,  // chunked layout
               float* __restrict__ hseq)         // [t][b][1024] fp32 or null
{
    extern __shared__ char smem[];
    half*  wsh  = (half*)smem;
    half*  wsl  = (half*)(smem + WS_PART_B);
    float* psum = (float*)(smem + PS_OFF);
    float* hsm  = (float*)(smem + HSM_OFF);
    float* xgs  = (float*)(smem + XG_OFF);
    uint64_t* hmb = (uint64_t*)(smem + MB_OFF);        // [2]
    uint64_t* xmb = (uint64_t*)(smem + MB_OFF + 16);   // [2]

    const int tid = threadIdx.x, lane = tid & 31, w = tid >> 5;
    const int mi = w & 1, ni = w >> 1;
    const int r = lane >> 2, q = lane & 3;
    const int bx = blockIdx.x;
    const int j0 = bx * 8;
    const float* xgb = xg + (size_t)bx * ((size_t)SEQ * BATCH * 32);

    if (tid == 0) {
        mbar_init(&hmb[0], 1); mbar_init(&hmb[1], 1);
        mbar_init(&xmb[0], 1); mbar_init(&xmb[1], 1);
    }

    // one-time: load + split Whh slice into smem (rows n = g*8+jl)
    for (int idx = tid; idx < 32 * 256; idx += NTHR) {
        int n = idx >> 8, kq = (idx & 255) * 4;
        int grow = (n >> 3) * HID + j0 + (n & 7);
        float4 v = *(const float4*)(Whh + (size_t)grow * HID + kq);
        half h0=__float2half(v.x), h1=__float2half(v.y), h2=__float2half(v.z), h3=__float2half(v.w);
        half* ph = wsh + n * WSS + kq;
        half* pl = wsl + n * WSS + kq;
        ph[0]=h0; ph[1]=h1; ph[2]=h2; ph[3]=h3;
        pl[0]=__float2half(v.x-__half2float(h0));
        pl[1]=__float2half(v.y-__half2float(h1));
        pl[2]=__float2half(v.z-__half2float(h2));
        pl[3]=__float2half(v.w-__half2float(h3));
    }
    __syncthreads();   // mbar init + weights visible

    if (tid == 0) {    // prologue: xg(0)
        mbar_expect(&xmb[0], XG_B);
        cpbulk(xgs, xgb, XG_B, &xmb[0]);
    }

    unsigned hph[2] = {0u, 0u};
    unsigned xph[2] = {0u, 0u};
    float creg[2] = {0.f, 0.f};

    for (int t = 0; t < SEQ; t++) {
        // step prologue: issue h chunk0 (t>0) and xg(t+1)
        if (tid == 0) {
            if (t > 0) {
                mbar_expect(&hmb[0], 32768u);
                const half* sH = hhi + (size_t)(t-1) * 65536;
                const half* sL = hlo + (size_t)(t-1) * 65536;
                cpbulk(smem + HS_OFF, sH, 16384u, &hmb[0]);
                cpbulk(smem + HS_OFF + 16384, sL, 16384u, &hmb[0]);
            }
            if (t + 1 < SEQ) {
                mbar_expect(&xmb[(t+1)&1], XG_B);
                cpbulk((char*)xgs + ((t+1)&1) * XG_B, xgb + (size_t)(t+1) * 2048, XG_B, &xmb[(t+1)&1]);
            }
        }

        if (t > 0) {
            float acc[2][4];
#pragma unroll
            for (int a = 0; a < 2; a++)
#pragma unroll
                for (int c = 0; c < 4; c++) acc[a][c] = 0.f;

            for (int c = 0; c < 8; c++) {
                if (c + 1 < 8) {
                    __syncthreads();   // compute(c-1) done -> buffer (c+1)&1 free
                    if (tid == 0) {
                        mbar_expect(&hmb[(c+1)&1], 32768u);
                        const half* sH = hhi + (size_t)(t-1) * 65536 + (size_t)(c+1) * 8192;
                        const half* sL = hlo + (size_t)(t-1) * 65536 + (size_t)(c+1) * 8192;
                        char* d = smem + HS_OFF + ((c+1)&1) * 32768;
                        cpbulk(d, sH, 16384u, &hmb[(c+1)&1]);
                        cpbulk(d + 16384, sL, 16384u, &hmb[(c+1)&1]);
                    }
                }
                mbar_wait(&hmb[c&1], hph[c&1]); hph[c&1] ^= 1u;

                const char* hb = smem + HS_OFF + (c&1) * 32768;
#pragma unroll
                for (int s = 0; s < 8; s++) {
                    const int kb = s * 16, kg = c * 128 + kb;
                    uint32_t Ah[2][4], Al[2][4], Bh[2], Bl[2];
#pragma unroll
                    for (int mt = 0; mt < 2; mt++) {
                        int lr = mi*32 + mt*16 + (lane & 15);
                        int wc = kb + ((lane >> 4) << 3);
                        uint32_t off = lr * 256 + ((uint32_t)((wc >> 3) ^ (lr & 7)) << 4);
                        ldsm4(Ah[mt], (const half*)(hb + off));
                        ldsm4(Al[mt], (const half*)(hb + 16384 + off));
                    }
                    ldsm2(Bh, wsh + (ni*8 + (lane&7))*WSS + kg + (((lane>>3)&1)<<3));
                    ldsm2(Bl, wsl + (ni*8 + (lane&7))*WSS + kg + (((lane>>3)&1)<<3));
#pragma unroll
                    for (int mt = 0; mt < 2; mt++) {
                        mma16816(acc[mt], Ah[mt], Bh);
                        mma16816(acc[mt], Ah[mt], Bl);
                        mma16816(acc[mt], Al[mt], Bh);
                    }
                }
            }

            // psum[b][n]
#pragma unroll
            for (int mt = 0; mt < 2; mt++) {
                int row = mi*32 + mt*16 + r, col = ni*8 + q*2;
                *(float2*)(psum + row*34 + col) = make_float2(acc[mt][0], acc[mt][1]);
                *(float2*)(psum + (row+8)*34 + col) = make_float2(acc[mt][2], acc[mt][3]);
            }
            __syncthreads();
        }

        // pointwise cell update
        mbar_wait(&xmb[t&1], xph[t&1]); xph[t&1] ^= 1u;
        const float* xt = xgs + (t&1) * 2048;
        float* h_out = hseq ? hseq + (size_t)t * BATCH * HID : (float*)0;
#pragma unroll
        for (int qq = 0; qq < 2; qq++) {
            int p = tid + NTHR * qq;
            int b = p >> 3, jl = p & 7;
            const float* xr = xt + b * 32 + jl;
            float ig = xr[0], fg = xr[8], gg = xr[16], og = xr[24];
            if (t > 0) {
                ig += psum[b*34 + jl];
                fg += psum[b*34 + 8 + jl];
                gg += psum[b*34 + 16 + jl];
                og += psum[b*34 + 24 + jl];
            }
            ig = sigmoid_fast(ig);
            fg = sigmoid_fast(fg);
            gg = tanh_fast(gg);
            og = sigmoid_fast(og);
            float cn = fg * creg[qq] + ig * gg;
            creg[qq] = cn;
            float hv = og * tanh_fast(cn);
            if (h_out) h_out[(size_t)b * HID + j0 + jl] = hv;
            hsm[b * 8 + jl] = hv;
        }
        __syncthreads();

        // 16B h stores in chunked-swizzled layout (row b: one segment)
        if (tid < 64) {
            int b = tid;
            uint4 uh, ul;
            half2* ph2 = (half2*)&uh;
            half2* pl2 = (half2*)&ul;
#pragma unroll
            for (int i = 0; i < 4; i++) {
                float a = hsm[b*8 + 2*i], cvl = hsm[b*8 + 2*i + 1];
                half ha = __float2half(a), hc = __float2half(cvl);
                ph2[i] = __halves2half2(ha, hc);
                pl2[i] = __halves2half2(__float2half(a - __half2float(ha)),
                                        __float2half(cvl - __half2float(hc)));
            }
            size_t o = (size_t)t * 65536 + ((size_t)(bx >> 4) * 64 + b) * 128
                       + ((size_t)((bx & 15) ^ (b & 7)) << 3);
            *(uint4*)(hhi + o) = uh;
            *(uint4*)(hlo + o) = ul;
        }
        grid_barrier((unsigned)(t + 1));
    }

    // self-reset barrier state for the next launch / graph replay
    if (blockIdx.x == 0) {
        if (tid > 0 && tid < NBLK) {
            while (ld_acq(&g_flags[tid * 8]) != 0u) { }
        }
        __syncthreads();
        if (tid == 0) st_rel(&g_gen, 0u);
    } else if (tid == 0) {
        st_rel(&g_flags[bx * 8], 0u);
    }

    __syncthreads();
    if (tid == 0) {
        mbar_inval(&hmb[0]); mbar_inval(&hmb[1]);
        mbar_inval(&xmb[0]); mbar_inval(&xmb[1]);
    }
}

// ---------------------------------------------------------------------------
__global__ void final_linear_kernel(const float* __restrict__ h_last,
                                    const float* __restrict__ Wl,
                                    const float* __restrict__ bl,
                                    float* __restrict__ y) {
    int b = blockIdx.x;
    __shared__ float red[128];
    float s = 0.f;
    for (int k = threadIdx.x; k < HID; k += 128)
        s += h_last[(size_t)b * HID + k] * Wl[k];
    red[threadIdx.x] = s;
    __syncthreads();
    for (int off = 64; off > 0; off >>= 1) {
        if (threadIdx.x < off) red[threadIdx.x] += red[threadIdx.x + off];
        __syncthreads();
    }
    if (threadIdx.x == 0) y[b] = red[0] + bl[0];
}

// ---------------------------------------------------------------------------
extern "C" void kernel_launch(void* const* d_in, const int* in_sizes, int n_in,
                              void* d_out, int out_size) {
    (void)in_sizes; (void)n_in; (void)out_size;
    const float* x    = (const float*)d_in[0];
    const float* Wih0 = (const float*)d_in[1];
    const float* Whh0 = (const float*)d_in[2];
    const float* bih0 = (const float*)d_in[3];
    const float* bhh0 = (const float*)d_in[4];
    const float* Wih1 = (const float*)d_in[5];
    const float* Whh1 = (const float*)d_in[6];
    const float* bih1 = (const float*)d_in[7];
    const float* bhh1 = (const float*)d_in[8];
    const float* Wlin = (const float*)d_in[9];
    const float* blin = (const float*)d_in[10];

    float* out      = (float*)d_out;
    float* lstm_out = out;
    float* ypred    = out + (size_t)SEQ * BATCH * HID;

    float *xg; half *hhi, *hlo, *whi, *wlo, *xhi, *xlo;
    cudaGetSymbolAddress((void**)&xg,  g_xg);
    cudaGetSymbolAddress((void**)&hhi, g_h_hi);
    cudaGetSymbolAddress((void**)&hlo, g_h_lo);
    cudaGetSymbolAddress((void**)&whi, g_w_hi);
    cudaGetSymbolAddress((void**)&wlo, g_w_lo);
    cudaGetSymbolAddress((void**)&xhi, g_x_hi);
    cudaGetSymbolAddress((void**)&xlo, g_x_lo);

    cudaFuncSetAttribute(lstm_layer_mma,
                         cudaFuncAttributeMaxDynamicSharedMemorySize, SMEM_TOT);

    const int M = SEQ * BATCH;
    dim3 gg(G4 / 64, M / 64);

    // Layer 0
    int nx = SEQ * BATCH * INP;
    split_fp16_kernel<<<nx/4/256, 256>>>(x, xhi, xlo, nx);
    int nw0 = G4 * INP;
    split_fp16_kernel<<<nw0/4/256, 256>>>(Wih0, whi, wlo, nw0);
    hgemm_split_kernel<<<gg, 256>>>(xhi, xlo, whi, wlo, bih0, bhh0, xg, M, INP, 0);
    lstm_layer_mma<<<NBLK, NTHR, SMEM_TOT>>>(xg, Whh0, hhi, hlo, (float*)0);

    // Layer 1
    int nw1 = G4 * HID;
    split_fp16_kernel<<<nw1/4/256, 256>>>(Wih1, whi, wlo, nw1);
    hgemm_split_kernel<<<gg, 256>>>(hhi, hlo, whi, wlo, bih1, bhh1, xg, M, HID, 1);
    lstm_layer_mma<<<NBLK, NTHR, SMEM_TOT>>>(xg, Whh1, hhi, hlo, lstm_out);

    // Head
    final_linear_kernel<<<BATCH, 128>>>(lstm_out + (size_t)(SEQ-1) * BATCH * HID,
                                        Wlin, blin, ypred);
}

// round 8
// speedup vs baseline: 1.8213x; 1.3677x over previous
#include <cuda_runtime.h>
#include <cuda_fp16.h>
#include <math.h>
#include <stdint.h>

#define SEQ   512
#define BATCH 64
#define INP   64
#define HID   1024
#define G4    (4 * HID)
#define NBLK  128
#define NTHR  256

// ---- static scratch ----
__device__ float g_xg[(size_t)SEQ * BATCH * G4];     // [jb][t*64+b][32]
__device__ half  g_h_hi[(size_t)SEQ * BATCH * HID];  // frag layout [t][mt][kt][lane]x8
__device__ half  g_w_hi[(size_t)G4 * HID];
__device__ half  g_w_lo[(size_t)G4 * HID];
__device__ half  g_x_hi[(size_t)SEQ * BATCH * INP];
__device__ half  g_x_lo[(size_t)SEQ * BATCH * INP];
__device__ unsigned g_flags[NBLK * 8];
__device__ unsigned g_gen;

// ---- helpers ----
__device__ __forceinline__ void mma16816(float c[4], const uint32_t* a, const uint32_t* b) {
    asm volatile("mma.sync.aligned.m16n8k16.row.col.f32.f16.f16.f32 "
        "{%0,%1,%2,%3}, {%4,%5,%6,%7}, {%8,%9}, {%0,%1,%2,%3};\n"
        : "+f"(c[0]), "+f"(c[1]), "+f"(c[2]), "+f"(c[3])
        : "r"(a[0]), "r"(a[1]), "r"(a[2]), "r"(a[3]), "r"(b[0]), "r"(b[1]));
}
__device__ __forceinline__ void ldsm4(uint32_t r[4], const half* p) {
    uint32_t a = (uint32_t)__cvta_generic_to_shared(p);
    asm volatile("ldmatrix.sync.aligned.m8n8.x4.shared.b16 {%0,%1,%2,%3}, [%4];\n"
        : "=r"(r[0]), "=r"(r[1]), "=r"(r[2]), "=r"(r[3]) : "r"(a));
}
__device__ __forceinline__ void ldsm2(uint32_t r[2], const half* p) {
    uint32_t a = (uint32_t)__cvta_generic_to_shared(p);
    asm volatile("ldmatrix.sync.aligned.m8n8.x2.shared.b16 {%0,%1}, [%2];\n"
        : "=r"(r[0]), "=r"(r[1]) : "r"(a));
}
__device__ __forceinline__ void cp16(void* dst, const void* src) {
    uint32_t d = (uint32_t)__cvta_generic_to_shared(dst);
    asm volatile("cp.async.cg.shared.global [%0], [%1], 16;\n" :: "r"(d), "l"(src));
}
#define CP_COMMIT() asm volatile("cp.async.commit_group;\n")
#define CP_WAIT0()  asm volatile("cp.async.wait_group 0;\n")

__device__ __forceinline__ void cpbulk(void* dst, const void* src, unsigned bytes, void* mbar) {
    uint32_t d = (uint32_t)__cvta_generic_to_shared(dst);
    uint32_t m = (uint32_t)__cvta_generic_to_shared(mbar);
    asm volatile("cp.async.bulk.shared::cta.global.mbarrier::complete_tx::bytes "
                 "[%0], [%1], %2, [%3];\n" :: "r"(d), "l"(src), "r"(bytes), "r"(m) : "memory");
}
__device__ __forceinline__ void mbar_init(void* mbar, unsigned cnt) {
    uint32_t m = (uint32_t)__cvta_generic_to_shared(mbar);
    asm volatile("mbarrier.init.shared.b64 [%0], %1;" :: "r"(m), "r"(cnt) : "memory");
}
__device__ __forceinline__ void mbar_inval(void* mbar) {
    uint32_t m = (uint32_t)__cvta_generic_to_shared(mbar);
    asm volatile("mbarrier.inval.shared.b64 [%0];" :: "r"(m) : "memory");
}
__device__ __forceinline__ void mbar_expect(void* mbar, unsigned bytes) {
    uint32_t m = (uint32_t)__cvta_generic_to_shared(mbar);
    asm volatile("mbarrier.arrive.expect_tx.shared.b64 _, [%0], %1;"
                 :: "r"(m), "r"(bytes) : "memory");
}
__device__ __forceinline__ void mbar_wait(void* mbar, unsigned parity) {
    uint32_t m = (uint32_t)__cvta_generic_to_shared(mbar);
    asm volatile(
        "{\n.reg .pred P;\n"
        "W%=: mbarrier.try_wait.parity.acquire.cta.shared::cta.b64 P, [%0], %1, 0x989680;\n"
        "@P bra D%=;\n"
        "bra W%=;\n"
        "D%=: }\n" :: "r"(m), "r"(parity) : "memory");
}
__device__ __forceinline__ unsigned ld_acq(const unsigned* p) {
    unsigned v;
    asm volatile("ld.acquire.gpu.u32 %0, [%1];" : "=r"(v) : "l"(p) : "memory");
    return v;
}
__device__ __forceinline__ void st_rel(unsigned* p, unsigned v) {
    asm volatile("st.release.gpu.u32 [%0], %1;" :: "l"(p), "r"(v) : "memory");
}
__device__ __forceinline__ float tanh_fast(float x) {
    float y;
    asm("tanh.approx.f32 %0, %1;" : "=f"(y) : "f"(x));
    return y;
}
__device__ __forceinline__ float sigmoid_fast(float x) {
    return 0.5f * tanh_fast(0.5f * x) + 0.5f;
}

__device__ __forceinline__ void grid_barrier(unsigned target) {
    __syncthreads();
    int tid = threadIdx.x;
    if (blockIdx.x == 0) {
        if (tid > 0 && tid < NBLK) {
            while (ld_acq(&g_flags[tid * 8]) < target) { }
        }
        __syncthreads();
        if (tid == 0) st_rel(&g_gen, target);
    } else {
        if (tid == 0) {
            st_rel(&g_flags[blockIdx.x * 8], target);
            while (ld_acq(&g_gen) < target) { }
        }
        __syncthreads();
    }
}

__global__ void split_fp16_kernel(const float* __restrict__ src,
                                  half* __restrict__ hi, half* __restrict__ lo, int n) {
    int i4 = (blockIdx.x * 256 + threadIdx.x) * 4;
    if (i4 >= n) return;
    float4 v = *(const float4*)(src + i4);
    half h0 = __float2half(v.x), h1 = __float2half(v.y);
    half h2 = __float2half(v.z), h3 = __float2half(v.w);
    hi[i4+0]=h0; hi[i4+1]=h1; hi[i4+2]=h2; hi[i4+3]=h3;
    lo[i4+0]=__float2half(v.x-__half2float(h0));
    lo[i4+1]=__float2half(v.y-__half2float(h1));
    lo[i4+2]=__float2half(v.z-__half2float(h2));
    lo[i4+3]=__float2half(v.w-__half2float(h3));
}

// ---------------------------------------------------------------------------
// xg[jb][m][g*8+jl] = A[m][K] @ W[4096][K]^T + b1 + b2
// achunked=0: A hi/lo in row-major (3-pass, smem-staged)
// achunked=1: A = h in frag layout, hi only (2-pass, register-direct LDG)
// ---------------------------------------------------------------------------
__global__ void __launch_bounds__(256)
hgemm_split_kernel(const half* __restrict__ Ahi, const half* __restrict__ Alo,
                   const half* __restrict__ Whi, const half* __restrict__ Wlo,
                   const float* __restrict__ b1, const float* __restrict__ b2,
                   float* __restrict__ C, int M, int K, int achunked) {
    __shared__ half sA[2][2][64 * 40];
    __shared__ half sB[2][2][64 * 40];
    const int tid = threadIdx.x, lane = tid & 31, w = tid >> 5;
    const int mi = w & 1, ni = w >> 1;
    const int r = lane >> 2, q = lane & 3;
    const int m0 = blockIdx.y * 64, n0 = blockIdx.x * 64;
    const int srow = tid >> 2, skq = (tid & 3) * 8;

    float acc[2][2][4];
#pragma unroll
    for (int a = 0; a < 2; a++)
#pragma unroll
        for (int b = 0; b < 2; b++)
#pragma unroll
            for (int c = 0; c < 4; c++) acc[a][b][c] = 0.f;

    const int NIT = K / 32;
    const half* fragB = Ahi + (size_t)(m0 >> 6) * 65536 + lane * 8;  // frag base (achunked)

    uint32_t Ac[2][2][4];   // [s][mtl] current A frags (achunked)
    if (achunked) {
#pragma unroll
        for (int s = 0; s < 2; s++)
#pragma unroll
            for (int mtl = 0; mtl < 2; mtl++) {
                uint4 v = *(const uint4*)(fragB + (((mi*2+mtl)*64 + s) * 256));
                Ac[s][mtl][0]=v.x; Ac[s][mtl][1]=v.y; Ac[s][mtl][2]=v.z; Ac[s][mtl][3]=v.w;
            }
    } else {
        cp16(&sA[0][0][srow*40+skq], Ahi + (size_t)(m0+srow)*K + skq);
        cp16(&sA[0][1][srow*40+skq], Alo + (size_t)(m0+srow)*K + skq);
    }
    cp16(&sB[0][0][srow*40+skq], Whi + (size_t)(n0+srow)*K + skq);
    cp16(&sB[0][1][srow*40+skq], Wlo + (size_t)(n0+srow)*K + skq);
    CP_COMMIT();

    for (int it = 0; it < NIT; it++) {
        CP_WAIT0();
        __syncthreads();
        uint32_t An[2][2][4];
        if (it + 1 < NIT) {
            int k0 = (it+1)*32, bf = (it+1) & 1;
            if (achunked) {
#pragma unroll
                for (int s = 0; s < 2; s++)
#pragma unroll
                    for (int mtl = 0; mtl < 2; mtl++) {
                        uint4 v = *(const uint4*)(fragB + (((mi*2+mtl)*64 + (it+1)*2 + s) * 256));
                        An[s][mtl][0]=v.x; An[s][mtl][1]=v.y; An[s][mtl][2]=v.z; An[s][mtl][3]=v.w;
                    }
            } else {
                cp16(&sA[bf][0][srow*40+skq], Ahi + (size_t)(m0+srow)*K + k0 + skq);
                cp16(&sA[bf][1][srow*40+skq], Alo + (size_t)(m0+srow)*K + k0 + skq);
            }
            cp16(&sB[bf][0][srow*40+skq], Whi + (size_t)(n0+srow)*K + k0 + skq);
            cp16(&sB[bf][1][srow*40+skq], Wlo + (size_t)(n0+srow)*K + k0 + skq);
            CP_COMMIT();
        }
        const half *Abh = sA[it&1][0], *Abl = sA[it&1][1];
        const half *Bbh = sB[it&1][0], *Bbl = sB[it&1][1];
#pragma unroll
        for (int s = 0; s < 2; s++) {
            const int kb = s * 16;
            uint32_t Ah[2][4], Al[2][4], Bh[2][2], Bl[2][2];
            if (achunked) {
#pragma unroll
                for (int mt = 0; mt < 2; mt++)
#pragma unroll
                    for (int z = 0; z < 4; z++) Ah[mt][z] = Ac[s][mt][z];
            } else {
#pragma unroll
                for (int mt = 0; mt < 2; mt++) {
                    ldsm4(Ah[mt], Abh + (mi*32 + mt*16 + (lane&15))*40 + kb + ((lane>>4)<<3));
                    ldsm4(Al[mt], Abl + (mi*32 + mt*16 + (lane&15))*40 + kb + ((lane>>4)<<3));
                }
            }
#pragma unroll
            for (int nt = 0; nt < 2; nt++) {
                ldsm2(Bh[nt], Bbh + (ni*16 + nt*8 + (lane&7))*40 + kb + (((lane>>3)&1)<<3));
                ldsm2(Bl[nt], Bbl + (ni*16 + nt*8 + (lane&7))*40 + kb + (((lane>>3)&1)<<3));
            }
#pragma unroll
            for (int mt = 0; mt < 2; mt++)
#pragma unroll
                for (int nt = 0; nt < 2; nt++) {
                    mma16816(acc[mt][nt], Ah[mt], Bh[nt]);
                    mma16816(acc[mt][nt], Ah[mt], Bl[nt]);
                    if (!achunked) mma16816(acc[mt][nt], Al[mt], Bh[nt]);
                }
        }
        if (achunked && it + 1 < NIT) {
#pragma unroll
            for (int s = 0; s < 2; s++)
#pragma unroll
                for (int mtl = 0; mtl < 2; mtl++)
#pragma unroll
                    for (int z = 0; z < 4; z++) Ac[s][mtl][z] = An[s][mtl][z];
        }
        __syncthreads();
    }
#pragma unroll
    for (int mt = 0; mt < 2; mt++)
#pragma unroll
        for (int nt = 0; nt < 2; nt++) {
            int row = m0 + mi*32 + mt*16 + r;
            int col = n0 + ni*16 + nt*8 + q*2;
            int g = col >> 10, rem = col & 1023, jb = rem >> 3, jl = rem & 7;
            float bs0 = b1[col] + b2[col], bs1 = b1[col+1] + b2[col+1];
            size_t base = (size_t)jb * ((size_t)SEQ * BATCH * 32) + (size_t)row * 32 + g*8 + jl;
            *(float2*)(C + base) = make_float2(acc[mt][nt][0]+bs0, acc[mt][nt][1]+bs1);
            *(float2*)(C + base + 8*32) = make_float2(acc[mt][nt][2]+bs0, acc[mt][nt][3]+bs1);
        }
}

// ---------------------------------------------------------------------------
// Persistent recurrence: register-direct A fragments from GMEM frag layout.
// Warps: mt = w&3 (m16 tile), ki = w>>2 (K half). 2 passes (W hi/lo), h hi.
// smem: W 132096 | psum 17408 | hsm 2048 | xg 16384 | mbar 16
// ---------------------------------------------------------------------------
#define WSS 1032
#define WS_PART_B (32 * WSS * 2)            // 66048
#define PS_OFF    (2 * WS_PART_B)           // 132096
#define HSM_OFF   (PS_OFF + 2*64*34*4)      // 149504
#define XG_OFF    (HSM_OFF + 2048)          // 151552
#define MB_OFF    (XG_OFF + 16384)          // 167936
#define SMEM_TOT  (MB_OFF + 16)             // 167952
#define XG_B      8192u

__global__ void __launch_bounds__(NTHR, 1)
lstm_layer_mma(const float* __restrict__ xg,     // [jb][t*64+b][32] incl. biases
               const float* __restrict__ Whh,    // [4H][H] fp32
               half* __restrict__ hfrag,         // frag layout
               float* __restrict__ hseq)         // [t][b][1024] fp32 or null
{
    extern __shared__ char smem[];
    half*  wsh  = (half*)smem;
    half*  wsl  = (half*)(smem + WS_PART_B);
    float* psum = (float*)(smem + PS_OFF);
    float* hsm  = (float*)(smem + HSM_OFF);
    float* xgs  = (float*)(smem + XG_OFF);
    uint64_t* xmb = (uint64_t*)(smem + MB_OFF);

    const int tid = threadIdx.x, lane = tid & 31, w = tid >> 5;
    const int mt = w & 3, ki = w >> 2;
    const int bx = blockIdx.x;
    const int j0 = bx * 8;
    const float* xgb = xg + (size_t)bx * ((size_t)SEQ * BATCH * 32);

    if (tid == 0) { mbar_init(&xmb[0], 1); mbar_init(&xmb[1], 1); }

    // one-time: Whh slice -> smem hi/lo (rows n = g*8+jl)
    for (int idx = tid; idx < 32 * 256; idx += NTHR) {
        int n = idx >> 8, kq = (idx & 255) * 4;
        int grow = (n >> 3) * HID + j0 + (n & 7);
        float4 v = *(const float4*)(Whh + (size_t)grow * HID + kq);
        half h0=__float2half(v.x), h1=__float2half(v.y), h2=__float2half(v.z), h3=__float2half(v.w);
        half* ph = wsh + n * WSS + kq;
        half* pl = wsl + n * WSS + kq;
        ph[0]=h0; ph[1]=h1; ph[2]=h2; ph[3]=h3;
        pl[0]=__float2half(v.x-__half2float(h0));
        pl[1]=__float2half(v.y-__half2float(h1));
        pl[2]=__float2half(v.z-__half2float(h2));
        pl[3]=__float2half(v.w-__half2float(h3));
    }
    __syncthreads();

    if (tid == 0) {    // prologue: xg(0)
        mbar_expect(&xmb[0], XG_B);
        cpbulk(xgs, xgb, XG_B, &xmb[0]);
    }

    unsigned xph[2] = {0u, 0u};
    float creg[2] = {0.f, 0.f};

    for (int t = 0; t < SEQ; t++) {
        if (tid == 0 && t + 1 < SEQ) {
            mbar_expect(&xmb[(t+1)&1], XG_B);
            cpbulk((char*)xgs + ((t+1)&1) * XG_B, xgb + (size_t)(t+1) * 2048, XG_B, &xmb[(t+1)&1]);
        }

        if (t > 0) {
            // per-warp frag base: ktiles [ki*32, ki*32+32)
            const half* hb = hfrag + (size_t)(t-1) * 65536
                             + ((size_t)mt * 64 + ki * 32) * 256 + lane * 8;
            uint32_t abuf[8][4];
#pragma unroll
            for (int i = 0; i < 8; i++) {
                uint4 v = *(const uint4*)(hb + i * 256);
                abuf[i][0]=v.x; abuf[i][1]=v.y; abuf[i][2]=v.z; abuf[i][3]=v.w;
            }
            float acc[4][4];
#pragma unroll
            for (int nt = 0; nt < 4; nt++)
#pragma unroll
                for (int c = 0; c < 4; c++) acc[nt][c] = 0.f;

            for (int p = 0; p < 4; p++) {
#pragma unroll
                for (int ii = 0; ii < 4; ii++) {
                    const int i0 = ii * 2;
                    const int ktl = p * 8 + i0;
                    const int kg = ki * 512 + ktl * 16;
                    uint32_t Bh4[4][4], Bl4[4][4];
#pragma unroll
                    for (int nt = 0; nt < 4; nt++) {
                        const int boff = (nt*8 + (lane&7))*WSS + kg + ((lane>>3)&3)*8;
                        ldsm4(Bh4[nt], wsh + boff);
                        ldsm4(Bl4[nt], wsl + boff);
                    }
#pragma unroll
                    for (int nt = 0; nt < 4; nt++) {
                        mma16816(acc[nt], abuf[i0],   Bh4[nt]);
                        mma16816(acc[nt], abuf[i0],   Bl4[nt]);
                        mma16816(acc[nt], abuf[i0+1], Bh4[nt]+2);
                        mma16816(acc[nt], abuf[i0+1], Bl4[nt]+2);
                    }
                    if (p < 3) {
                        uint4 v0 = *(const uint4*)(hb + (ktl + 8) * 256);
                        abuf[i0][0]=v0.x; abuf[i0][1]=v0.y; abuf[i0][2]=v0.z; abuf[i0][3]=v0.w;
                        uint4 v1 = *(const uint4*)(hb + (ktl + 9) * 256);
                        abuf[i0+1][0]=v1.x; abuf[i0+1][1]=v1.y; abuf[i0+1][2]=v1.z; abuf[i0+1][3]=v1.w;
                    }
                }
            }
            // psum[ki][row][col]
            int prow = mt*16 + (lane>>2), pcol = (lane&3)*2;
#pragma unroll
            for (int nt = 0; nt < 4; nt++) {
                *(float2*)(psum + ((ki*64 + prow)*34) + nt*8 + pcol) =
                    make_float2(acc[nt][0], acc[nt][1]);
                *(float2*)(psum + ((ki*64 + prow + 8)*34) + nt*8 + pcol) =
                    make_float2(acc[nt][2], acc[nt][3]);
            }
            __syncthreads();
        }

        // pointwise cell update
        mbar_wait(&xmb[t&1], xph[t&1]); xph[t&1] ^= 1u;
        const float* xt = xgs + (t&1) * 2048;
        float* h_out = hseq ? hseq + (size_t)t * BATCH * HID : (float*)0;
#pragma unroll
        for (int qq = 0; qq < 2; qq++) {
            int p = tid + NTHR * qq;
            int b = p >> 3, jl = p & 7;
            const float* xr = xt + b * 32 + jl;
            float ig = xr[0], fg = xr[8], gg = xr[16], og = xr[24];
            if (t > 0) {
                ig += psum[(b)*34 + jl]        + psum[(64+b)*34 + jl];
                fg += psum[(b)*34 + 8 + jl]    + psum[(64+b)*34 + 8 + jl];
                gg += psum[(b)*34 + 16 + jl]   + psum[(64+b)*34 + 16 + jl];
                og += psum[(b)*34 + 24 + jl]   + psum[(64+b)*34 + 24 + jl];
            }
            ig = sigmoid_fast(ig);
            fg = sigmoid_fast(fg);
            gg = tanh_fast(gg);
            og = sigmoid_fast(og);
            float cn = fg * creg[qq] + ig * gg;
            creg[qq] = cn;
            float hv = og * tanh_fast(cn);
            if (h_out) h_out[(size_t)b * HID + j0 + jl] = hv;
            hsm[b * 8 + jl] = hv;
        }
        __syncthreads();

        // h fragment stores: tid<128 -> one 8B segment each
        if (tid < 128) {
            int fm = tid >> 5, l = tid & 31;
            int b1 = fm*16 + (l>>2), jl = (l&3)*2;
            half2 p0 = __floats2half2_rn(hsm[b1*8 + jl],       hsm[b1*8 + jl + 1]);
            half2 p1 = __floats2half2_rn(hsm[(b1+8)*8 + jl],   hsm[(b1+8)*8 + jl + 1]);
            uint2 u = make_uint2(*(unsigned*)&p0, *(unsigned*)&p1);
            size_t o = (size_t)t * 65536 + ((size_t)fm * 64 + (bx >> 1)) * 256
                       + l * 8 + (bx & 1) * 4;
            *(uint2*)(hfrag + o) = u;
        }
        grid_barrier((unsigned)(t + 1));
    }

    // self-reset barrier for next launch / replay
    int tid2 = threadIdx.x;
    if (blockIdx.x == 0) {
        if (tid2 > 0 && tid2 < NBLK) {
            while (ld_acq(&g_flags[tid2 * 8]) != 0u) { }
        }
        __syncthreads();
        if (tid2 == 0) st_rel(&g_gen, 0u);
    } else if (tid2 == 0) {
        st_rel(&g_flags[bx * 8], 0u);
    }

    __syncthreads();
    if (tid == 0) { mbar_inval(&xmb[0]); mbar_inval(&xmb[1]); }
}

// ---------------------------------------------------------------------------
__global__ void final_linear_kernel(const float* __restrict__ h_last,
                                    const float* __restrict__ Wl,
                                    const float* __restrict__ bl,
                                    float* __restrict__ y) {
    int b = blockIdx.x;
    __shared__ float red[128];
    float s = 0.f;
    for (int k = threadIdx.x; k < HID; k += 128)
        s += h_last[(size_t)b * HID + k] * Wl[k];
    red[threadIdx.x] = s;
    __syncthreads();
    for (int off = 64; off > 0; off >>= 1) {
        if (threadIdx.x < off) red[threadIdx.x] += red[threadIdx.x + off];
        __syncthreads();
    }
    if (threadIdx.x == 0) y[b] = red[0] + bl[0];
}

// ---------------------------------------------------------------------------
extern "C" void kernel_launch(void* const* d_in, const int* in_sizes, int n_in,
                              void* d_out, int out_size) {
    (void)in_sizes; (void)n_in; (void)out_size;
    const float* x    = (const float*)d_in[0];
    const float* Wih0 = (const float*)d_in[1];
    const float* Whh0 = (const float*)d_in[2];
    const float* bih0 = (const float*)d_in[3];
    const float* bhh0 = (const float*)d_in[4];
    const float* Wih1 = (const float*)d_in[5];
    const float* Whh1 = (const float*)d_in[6];
    const float* bih1 = (const float*)d_in[7];
    const float* bhh1 = (const float*)d_in[8];
    const float* Wlin = (const float*)d_in[9];
    const float* blin = (const float*)d_in[10];

    float* out      = (float*)d_out;
    float* lstm_out = out;
    float* ypred    = out + (size_t)SEQ * BATCH * HID;

    float *xg; half *hhi, *whi, *wlo, *xhi, *xlo;
    cudaGetSymbolAddress((void**)&xg,  g_xg);
    cudaGetSymbolAddress((void**)&hhi, g_h_hi);
    cudaGetSymbolAddress((void**)&whi, g_w_hi);
    cudaGetSymbolAddress((void**)&wlo, g_w_lo);
    cudaGetSymbolAddress((void**)&xhi, g_x_hi);
    cudaGetSymbolAddress((void**)&xlo, g_x_lo);

    cudaFuncSetAttribute(lstm_layer_mma,
                         cudaFuncAttributeMaxDynamicSharedMemorySize, SMEM_TOT);

    const int M = SEQ * BATCH;
    dim3 gg(G4 / 64, M / 64);

    // Layer 0
    int nx = SEQ * BATCH * INP;
    split_fp16_kernel<<<nx/4/256, 256>>>(x, xhi, xlo, nx);
    int nw0 = G4 * INP;
    split_fp16_kernel<<<nw0/4/256, 256>>>(Wih0, whi, wlo, nw0);
    hgemm_split_kernel<<<gg, 256>>>(xhi, xlo, whi, wlo, bih0, bhh0, xg, M, INP, 0);
    lstm_layer_mma<<<NBLK, NTHR, SMEM_TOT>>>(xg, Whh0, hhi, (float*)0);

    // Layer 1
    int nw1 = G4 * HID;
    split_fp16_kernel<<<nw1/4/256, 256>>>(Wih1, whi, wlo, nw1);
    hgemm_split_kernel<<<gg, 256>>>(hhi, (const half*)0, whi, wlo, bih1, bhh1, xg, M, HID, 1);
    lstm_layer_mma<<<NBLK, NTHR, SMEM_TOT>>>(xg, Whh1, hhi, lstm_out);

    // Head
    final_linear_kernel<<<BATCH, 128>>>(lstm_out + (size_t)(SEQ-1) * BATCH * HID,
                                        Wlin, blin, ypred);
}

// round 9
// speedup vs baseline: 1.8859x; 1.0354x over previous
#include <cuda_runtime.h>
#include <cuda_fp16.h>
#include <math.h>
#include <stdint.h>

#define SEQ   512
#define BATCH 64
#define INP   64
#define HID   1024
#define G4    (4 * HID)
#define NBLK  128
#define NTHR  256

// ---- static scratch ----
__device__ float g_xg[(size_t)SEQ * BATCH * G4];     // [jb][t*64+b][32]
__device__ half  g_h_hi[(size_t)SEQ * BATCH * HID];  // frag layout [t][mt][kt][lane]x8
__device__ half  g_w_hi[(size_t)G4 * HID];
__device__ half  g_w_lo[(size_t)G4 * HID];
__device__ half  g_x_hi[(size_t)SEQ * BATCH * INP];
__device__ half  g_x_lo[(size_t)SEQ * BATCH * INP];
__device__ unsigned g_flags[NBLK * 8];   // padded 32B; zero at rest
__device__ unsigned g_done;              // end-of-kernel reset counter

// ---- helpers ----
__device__ __forceinline__ void mma16816(float c[4], const uint32_t* a, const uint32_t* b) {
    asm volatile("mma.sync.aligned.m16n8k16.row.col.f32.f16.f16.f32 "
        "{%0,%1,%2,%3}, {%4,%5,%6,%7}, {%8,%9}, {%0,%1,%2,%3};\n"
        : "+f"(c[0]), "+f"(c[1]), "+f"(c[2]), "+f"(c[3])
        : "r"(a[0]), "r"(a[1]), "r"(a[2]), "r"(a[3]), "r"(b[0]), "r"(b[1]));
}
__device__ __forceinline__ void ldsm4(uint32_t r[4], const half* p) {
    uint32_t a = (uint32_t)__cvta_generic_to_shared(p);
    asm volatile("ldmatrix.sync.aligned.m8n8.x4.shared.b16 {%0,%1,%2,%3}, [%4];\n"
        : "=r"(r[0]), "=r"(r[1]), "=r"(r[2]), "=r"(r[3]) : "r"(a));
}
__device__ __forceinline__ void ldsm2(uint32_t r[2], const half* p) {
    uint32_t a = (uint32_t)__cvta_generic_to_shared(p);
    asm volatile("ldmatrix.sync.aligned.m8n8.x2.shared.b16 {%0,%1}, [%2];\n"
        : "=r"(r[0]), "=r"(r[1]) : "r"(a));
}
__device__ __forceinline__ void cp16(void* dst, const void* src) {
    uint32_t d = (uint32_t)__cvta_generic_to_shared(dst);
    asm volatile("cp.async.cg.shared.global [%0], [%1], 16;\n" :: "r"(d), "l"(src));
}
#define CP_COMMIT() asm volatile("cp.async.commit_group;\n")
#define CP_WAIT0()  asm volatile("cp.async.wait_group 0;\n")

__device__ __forceinline__ void cpbulk(void* dst, const void* src, unsigned bytes, void* mbar) {
    uint32_t d = (uint32_t)__cvta_generic_to_shared(dst);
    uint32_t m = (uint32_t)__cvta_generic_to_shared(mbar);
    asm volatile("cp.async.bulk.shared::cta.global.mbarrier::complete_tx::bytes "
                 "[%0], [%1], %2, [%3];\n" :: "r"(d), "l"(src), "r"(bytes), "r"(m) : "memory");
}
__device__ __forceinline__ void mbar_init(void* mbar, unsigned cnt) {
    uint32_t m = (uint32_t)__cvta_generic_to_shared(mbar);
    asm volatile("mbarrier.init.shared.b64 [%0], %1;" :: "r"(m), "r"(cnt) : "memory");
}
__device__ __forceinline__ void mbar_inval(void* mbar) {
    uint32_t m = (uint32_t)__cvta_generic_to_shared(mbar);
    asm volatile("mbarrier.inval.shared.b64 [%0];" :: "r"(m) : "memory");
}
__device__ __forceinline__ void mbar_expect(void* mbar, unsigned bytes) {
    uint32_t m = (uint32_t)__cvta_generic_to_shared(mbar);
    asm volatile("mbarrier.arrive.expect_tx.shared.b64 _, [%0], %1;"
                 :: "r"(m), "r"(bytes) : "memory");
}
__device__ __forceinline__ void mbar_wait(void* mbar, unsigned parity) {
    uint32_t m = (uint32_t)__cvta_generic_to_shared(mbar);
    asm volatile(
        "{\n.reg .pred P;\n"
        "W%=: mbarrier.try_wait.parity.acquire.cta.shared::cta.b64 P, [%0], %1, 0x989680;\n"
        "@P bra D%=;\n"
        "bra W%=;\n"
        "D%=: }\n" :: "r"(m), "r"(parity) : "memory");
}
__device__ __forceinline__ unsigned ld_acq(const unsigned* p) {
    unsigned v;
    asm volatile("ld.acquire.gpu.u32 %0, [%1];" : "=r"(v) : "l"(p) : "memory");
    return v;
}
__device__ __forceinline__ void st_rel(unsigned* p, unsigned v) {
    asm volatile("st.release.gpu.u32 [%0], %1;" :: "l"(p), "r"(v) : "memory");
}
__device__ __forceinline__ float tanh_fast(float x) {
    float y;
    asm("tanh.approx.f32 %0, %1;" : "=f"(y) : "f"(x));
    return y;
}
__device__ __forceinline__ float sigmoid_fast(float x) {
    return 0.5f * tanh_fast(0.5f * x) + 0.5f;
}

// Single-hop grid barrier: every block stores its flag; every block's
// first NBLK threads poll all flags in parallel. Monotonic targets.
__device__ __forceinline__ void grid_barrier(unsigned target) {
    __syncthreads();   // all threads' writes precede the release store
    int tid = threadIdx.x;
    if (tid == 0) st_rel(&g_flags[blockIdx.x * 8], target);
    if (tid < NBLK) {
        while (ld_acq(&g_flags[tid * 8]) < target) { }
    }
    __syncthreads();
}

__global__ void split_fp16_kernel(const float* __restrict__ src,
                                  half* __restrict__ hi, half* __restrict__ lo, int n) {
    int i4 = (blockIdx.x * 256 + threadIdx.x) * 4;
    if (i4 >= n) return;
    float4 v = *(const float4*)(src + i4);
    half h0 = __float2half(v.x), h1 = __float2half(v.y);
    half h2 = __float2half(v.z), h3 = __float2half(v.w);
    hi[i4+0]=h0; hi[i4+1]=h1; hi[i4+2]=h2; hi[i4+3]=h3;
    lo[i4+0]=__float2half(v.x-__half2float(h0));
    lo[i4+1]=__float2half(v.y-__half2float(h1));
    lo[i4+2]=__float2half(v.z-__half2float(h2));
    lo[i4+3]=__float2half(v.w-__half2float(h3));
}

// ---------------------------------------------------------------------------
// xg[jb][m][g*8+jl] = A[m][K] @ W[4096][K]^T + b1 + b2
// achunked=0: A hi/lo row-major (3-pass). achunked=1: A = h frag layout (2-pass).
// ---------------------------------------------------------------------------
__global__ void __launch_bounds__(256)
hgemm_split_kernel(const half* __restrict__ Ahi, const half* __restrict__ Alo,
                   const half* __restrict__ Whi, const half* __restrict__ Wlo,
                   const float* __restrict__ b1, const float* __restrict__ b2,
                   float* __restrict__ C, int M, int K, int achunked) {
    __shared__ half sA[2][2][64 * 40];
    __shared__ half sB[2][2][64 * 40];
    const int tid = threadIdx.x, lane = tid & 31, w = tid >> 5;
    const int mi = w & 1, ni = w >> 1;
    const int r = lane >> 2, q = lane & 3;
    const int m0 = blockIdx.y * 64, n0 = blockIdx.x * 64;
    const int srow = tid >> 2, skq = (tid & 3) * 8;

    float acc[2][2][4];
#pragma unroll
    for (int a = 0; a < 2; a++)
#pragma unroll
        for (int b = 0; b < 2; b++)
#pragma unroll
            for (int c = 0; c < 4; c++) acc[a][b][c] = 0.f;

    const int NIT = K / 32;
    const half* fragB = Ahi + (size_t)(m0 >> 6) * 65536 + lane * 8;

    uint32_t Ac[2][2][4];
    if (achunked) {
#pragma unroll
        for (int s = 0; s < 2; s++)
#pragma unroll
            for (int mtl = 0; mtl < 2; mtl++) {
                uint4 v = *(const uint4*)(fragB + (((mi*2+mtl)*64 + s) * 256));
                Ac[s][mtl][0]=v.x; Ac[s][mtl][1]=v.y; Ac[s][mtl][2]=v.z; Ac[s][mtl][3]=v.w;
            }
    } else {
        cp16(&sA[0][0][srow*40+skq], Ahi + (size_t)(m0+srow)*K + skq);
        cp16(&sA[0][1][srow*40+skq], Alo + (size_t)(m0+srow)*K + skq);
    }
    cp16(&sB[0][0][srow*40+skq], Whi + (size_t)(n0+srow)*K + skq);
    cp16(&sB[0][1][srow*40+skq], Wlo + (size_t)(n0+srow)*K + skq);
    CP_COMMIT();

    for (int it = 0; it < NIT; it++) {
        CP_WAIT0();
        __syncthreads();
        uint32_t An[2][2][4];
        if (it + 1 < NIT) {
            int k0 = (it+1)*32, bf = (it+1) & 1;
            if (achunked) {
#pragma unroll
                for (int s = 0; s < 2; s++)
#pragma unroll
                    for (int mtl = 0; mtl < 2; mtl++) {
                        uint4 v = *(const uint4*)(fragB + (((mi*2+mtl)*64 + (it+1)*2 + s) * 256));
                        An[s][mtl][0]=v.x; An[s][mtl][1]=v.y; An[s][mtl][2]=v.z; An[s][mtl][3]=v.w;
                    }
            } else {
                cp16(&sA[bf][0][srow*40+skq], Ahi + (size_t)(m0+srow)*K + k0 + skq);
                cp16(&sA[bf][1][srow*40+skq], Alo + (size_t)(m0+srow)*K + k0 + skq);
            }
            cp16(&sB[bf][0][srow*40+skq], Whi + (size_t)(n0+srow)*K + k0 + skq);
            cp16(&sB[bf][1][srow*40+skq], Wlo + (size_t)(n0+srow)*K + k0 + skq);
            CP_COMMIT();
        }
        const half *Abh = sA[it&1][0], *Abl = sA[it&1][1];
        const half *Bbh = sB[it&1][0], *Bbl = sB[it&1][1];
#pragma unroll
        for (int s = 0; s < 2; s++) {
            const int kb = s * 16;
            uint32_t Ah[2][4], Al[2][4], Bh[2][2], Bl[2][2];
            if (achunked) {
#pragma unroll
                for (int mt = 0; mt < 2; mt++)
#pragma unroll
                    for (int z = 0; z < 4; z++) Ah[mt][z] = Ac[s][mt][z];
            } else {
#pragma unroll
                for (int mt = 0; mt < 2; mt++) {
                    ldsm4(Ah[mt], Abh + (mi*32 + mt*16 + (lane&15))*40 + kb + ((lane>>4)<<3));
                    ldsm4(Al[mt], Abl + (mi*32 + mt*16 + (lane&15))*40 + kb + ((lane>>4)<<3));
                }
            }
#pragma unroll
            for (int nt = 0; nt < 2; nt++) {
                ldsm2(Bh[nt], Bbh + (ni*16 + nt*8 + (lane&7))*40 + kb + (((lane>>3)&1)<<3));
                ldsm2(Bl[nt], Bbl + (ni*16 + nt*8 + (lane&7))*40 + kb + (((lane>>3)&1)<<3));
            }
#pragma unroll
            for (int mt = 0; mt < 2; mt++)
#pragma unroll
                for (int nt = 0; nt < 2; nt++) {
                    mma16816(acc[mt][nt], Ah[mt], Bh[nt]);
                    mma16816(acc[mt][nt], Ah[mt], Bl[nt]);
                    if (!achunked) mma16816(acc[mt][nt], Al[mt], Bh[nt]);
                }
        }
        if (achunked && it + 1 < NIT) {
#pragma unroll
            for (int s = 0; s < 2; s++)
#pragma unroll
                for (int mtl = 0; mtl < 2; mtl++)
#pragma unroll
                    for (int z = 0; z < 4; z++) Ac[s][mtl][z] = An[s][mtl][z];
        }
        __syncthreads();
    }
#pragma unroll
    for (int mt = 0; mt < 2; mt++)
#pragma unroll
        for (int nt = 0; nt < 2; nt++) {
            int row = m0 + mi*32 + mt*16 + r;
            int col = n0 + ni*16 + nt*8 + q*2;
            int g = col >> 10, rem = col & 1023, jb = rem >> 3, jl = rem & 7;
            float bs0 = b1[col] + b2[col], bs1 = b1[col+1] + b2[col+1];
            size_t base = (size_t)jb * ((size_t)SEQ * BATCH * 32) + (size_t)row * 32 + g*8 + jl;
            *(float2*)(C + base) = make_float2(acc[mt][nt][0]+bs0, acc[mt][nt][1]+bs1);
            *(float2*)(C + base + 8*32) = make_float2(acc[mt][nt][2]+bs0, acc[mt][nt][3]+bs1);
        }
}

// ---------------------------------------------------------------------------
// Persistent recurrence: register-direct A frags, fp16 W (single pass).
// Warps: mt = w&3, ki = w>>2. smem: W 66048 | psum 17408 | hsm 2048 | xg 16384 | mbar 16
// ---------------------------------------------------------------------------
#define WSS 1032
#define WS_PART_B (32 * WSS * 2)            // 66048
#define PS_OFF    WS_PART_B                 // 66048
#define HSM_OFF   (PS_OFF + 2*64*34*4)      // 83456
#define XG_OFF    (HSM_OFF + 2048)          // 85504
#define MB_OFF    (XG_OFF + 16384)          // 101888
#define SMEM_TOT  (MB_OFF + 16)             // 101904
#define XG_B      8192u

__global__ void __launch_bounds__(NTHR, 1)
lstm_layer_mma(const float* __restrict__ xg,     // [jb][t*64+b][32] incl. biases
               const float* __restrict__ Whh,    // [4H][H] fp32
               half* __restrict__ hfrag,         // frag layout
               float* __restrict__ hseq)         // [t][b][1024] fp32 or null
{
    extern __shared__ char smem[];
    half*  wsh  = (half*)smem;
    float* psum = (float*)(smem + PS_OFF);
    float* hsm  = (float*)(smem + HSM_OFF);
    float* xgs  = (float*)(smem + XG_OFF);
    uint64_t* xmb = (uint64_t*)(smem + MB_OFF);

    const int tid = threadIdx.x, lane = tid & 31, w = tid >> 5;
    const int mt = w & 3, ki = w >> 2;
    const int bx = blockIdx.x;
    const int j0 = bx * 8;
    const float* xgb = xg + (size_t)bx * ((size_t)SEQ * BATCH * 32);

    if (tid == 0) { mbar_init(&xmb[0], 1); mbar_init(&xmb[1], 1); }

    // one-time: Whh slice -> smem fp16 (rows n = g*8+jl)
    for (int idx = tid; idx < 32 * 256; idx += NTHR) {
        int n = idx >> 8, kq = (idx & 255) * 4;
        int grow = (n >> 3) * HID + j0 + (n & 7);
        float4 v = *(const float4*)(Whh + (size_t)grow * HID + kq);
        half* ph = wsh + n * WSS + kq;
        ph[0]=__float2half(v.x); ph[1]=__float2half(v.y);
        ph[2]=__float2half(v.z); ph[3]=__float2half(v.w);
    }
    __syncthreads();

    if (tid == 0) {    // prologue: xg(0)
        mbar_expect(&xmb[0], XG_B);
        cpbulk(xgs, xgb, XG_B, &xmb[0]);
    }

    unsigned xph[2] = {0u, 0u};
    float creg[2] = {0.f, 0.f};

    for (int t = 0; t < SEQ; t++) {
        if (tid == 0 && t + 1 < SEQ) {
            mbar_expect(&xmb[(t+1)&1], XG_B);
            cpbulk((char*)xgs + ((t+1)&1) * XG_B, xgb + (size_t)(t+1) * 2048, XG_B, &xmb[(t+1)&1]);
        }

        if (t > 0) {
            const half* hb = hfrag + (size_t)(t-1) * 65536
                             + ((size_t)mt * 64 + ki * 32) * 256 + lane * 8;
            uint32_t abuf[8][4];
#pragma unroll
            for (int i = 0; i < 8; i++) {
                uint4 v = *(const uint4*)(hb + i * 256);
                abuf[i][0]=v.x; abuf[i][1]=v.y; abuf[i][2]=v.z; abuf[i][3]=v.w;
            }
            float acc[4][4];
#pragma unroll
            for (int nt = 0; nt < 4; nt++)
#pragma unroll
                for (int c = 0; c < 4; c++) acc[nt][c] = 0.f;

            for (int p = 0; p < 4; p++) {
#pragma unroll
                for (int ii = 0; ii < 4; ii++) {
                    const int i0 = ii * 2;
                    const int ktl = p * 8 + i0;
                    const int kg = ki * 512 + ktl * 16;
                    uint32_t Bh4[4][4];
#pragma unroll
                    for (int nt = 0; nt < 4; nt++)
                        ldsm4(Bh4[nt], wsh + (nt*8 + (lane&7))*WSS + kg + ((lane>>3)&3)*8);
#pragma unroll
                    for (int nt = 0; nt < 4; nt++) {
                        mma16816(acc[nt], abuf[i0],   Bh4[nt]);
                        mma16816(acc[nt], abuf[i0+1], Bh4[nt]+2);
                    }
                    if (p < 3) {
                        uint4 v0 = *(const uint4*)(hb + (ktl + 8) * 256);
                        abuf[i0][0]=v0.x; abuf[i0][1]=v0.y; abuf[i0][2]=v0.z; abuf[i0][3]=v0.w;
                        uint4 v1 = *(const uint4*)(hb + (ktl + 9) * 256);
                        abuf[i0+1][0]=v1.x; abuf[i0+1][1]=v1.y; abuf[i0+1][2]=v1.z; abuf[i0+1][3]=v1.w;
                    }
                }
            }
            int prow = mt*16 + (lane>>2), pcol = (lane&3)*2;
#pragma unroll
            for (int nt = 0; nt < 4; nt++) {
                *(float2*)(psum + ((ki*64 + prow)*34) + nt*8 + pcol) =
                    make_float2(acc[nt][0], acc[nt][1]);
                *(float2*)(psum + ((ki*64 + prow + 8)*34) + nt*8 + pcol) =
                    make_float2(acc[nt][2], acc[nt][3]);
            }
            __syncthreads();
        }

        // pointwise cell update
        mbar_wait(&xmb[t&1], xph[t&1]); xph[t&1] ^= 1u;
        const float* xt = xgs + (t&1) * 2048;
        float* h_out = hseq ? hseq + (size_t)t * BATCH * HID : (float*)0;
#pragma unroll
        for (int qq = 0; qq < 2; qq++) {
            int p = tid + NTHR * qq;
            int b = p >> 3, jl = p & 7;
            const float* xr = xt + b * 32 + jl;
            float ig = xr[0], fg = xr[8], gg = xr[16], og = xr[24];
            if (t > 0) {
                ig += psum[(b)*34 + jl]      + psum[(64+b)*34 + jl];
                fg += psum[(b)*34 + 8 + jl]  + psum[(64+b)*34 + 8 + jl];
                gg += psum[(b)*34 + 16 + jl] + psum[(64+b)*34 + 16 + jl];
                og += psum[(b)*34 + 24 + jl] + psum[(64+b)*34 + 24 + jl];
            }
            ig = sigmoid_fast(ig);
            fg = sigmoid_fast(fg);
            gg = tanh_fast(gg);
            og = sigmoid_fast(og);
            float cn = fg * creg[qq] + ig * gg;
            creg[qq] = cn;
            float hv = og * tanh_fast(cn);
            if (h_out) h_out[(size_t)b * HID + j0 + jl] = hv;
            hsm[b * 8 + jl] = hv;
        }
        __syncthreads();

        // h fragment stores: tid<128 -> one 8B segment each
        if (tid < 128) {
            int fm = tid >> 5, l = tid & 31;
            int b1 = fm*16 + (l>>2), jl = (l&3)*2;
            half2 p0 = __floats2half2_rn(hsm[b1*8 + jl],     hsm[b1*8 + jl + 1]);
            half2 p1 = __floats2half2_rn(hsm[(b1+8)*8 + jl], hsm[(b1+8)*8 + jl + 1]);
            uint2 u = make_uint2(*(unsigned*)&p0, *(unsigned*)&p1);
            size_t o = (size_t)t * 65536 + ((size_t)fm * 64 + (bx >> 1)) * 256
                       + l * 8 + (bx & 1) * 4;
            *(uint2*)(hfrag + o) = u;
        }
        grid_barrier((unsigned)(t + 1));
    }

    // end-of-kernel reset: safe because every block has finished polling
    // before it increments g_done; the last block resets all state.
    if (tid == 0) {
        unsigned c = atomicAdd(&g_done, 1u);
        if (c == NBLK - 1u) {
            for (int i = 0; i < NBLK; i++) g_flags[i * 8] = 0u;
            __threadfence();
            g_done = 0u;
        }
    }
    __syncthreads();
    if (tid == 0) { mbar_inval(&xmb[0]); mbar_inval(&xmb[1]); }
}

// ---------------------------------------------------------------------------
__global__ void final_linear_kernel(const float* __restrict__ h_last,
                                    const float* __restrict__ Wl,
                                    const float* __restrict__ bl,
                                    float* __restrict__ y) {
    int b = blockIdx.x;
    __shared__ float red[128];
    float s = 0.f;
    for (int k = threadIdx.x; k < HID; k += 128)
        s += h_last[(size_t)b * HID + k] * Wl[k];
    red[threadIdx.x] = s;
    __syncthreads();
    for (int off = 64; off > 0; off >>= 1) {
        if (threadIdx.x < off) red[threadIdx.x] += red[threadIdx.x + off];
        __syncthreads();
    }
    if (threadIdx.x == 0) y[b] = red[0] + bl[0];
}

// ---------------------------------------------------------------------------
extern "C" void kernel_launch(void* const* d_in, const int* in_sizes, int n_in,
                              void* d_out, int out_size) {
    (void)in_sizes; (void)n_in; (void)out_size;
    const float* x    = (const float*)d_in[0];
    const float* Wih0 = (const float*)d_in[1];
    const float* Whh0 = (const float*)d_in[2];
    const float* bih0 = (const float*)d_in[3];
    const float* bhh0 = (const float*)d_in[4];
    const float* Wih1 = (const float*)d_in[5];
    const float* Whh1 = (const float*)d_in[6];
    const float* bih1 = (const float*)d_in[7];
    const float* bhh1 = (const float*)d_in[8];
    const float* Wlin = (const float*)d_in[9];
    const float* blin = (const float*)d_in[10];

    float* out      = (float*)d_out;
    float* lstm_out = out;
    float* ypred    = out + (size_t)SEQ * BATCH * HID;

    float *xg; half *hhi, *whi, *wlo, *xhi, *xlo;
    cudaGetSymbolAddress((void**)&xg,  g_xg);
    cudaGetSymbolAddress((void**)&hhi, g_h_hi);
    cudaGetSymbolAddress((void**)&whi, g_w_hi);
    cudaGetSymbolAddress((void**)&wlo, g_w_lo);
    cudaGetSymbolAddress((void**)&xhi, g_x_hi);
    cudaGetSymbolAddress((void**)&xlo, g_x_lo);

    cudaFuncSetAttribute(lstm_layer_mma,
                         cudaFuncAttributeMaxDynamicSharedMemorySize, SMEM_TOT);

    const int M = SEQ * BATCH;
    dim3 gg(G4 / 64, M / 64);

    // Layer 0
    int nx = SEQ * BATCH * INP;
    split_fp16_kernel<<<nx/4/256, 256>>>(x, xhi, xlo, nx);
    int nw0 = G4 * INP;
    split_fp16_kernel<<<nw0/4/256, 256>>>(Wih0, whi, wlo, nw0);
    hgemm_split_kernel<<<gg, 256>>>(xhi, xlo, whi, wlo, bih0, bhh0, xg, M, INP, 0);
    lstm_layer_mma<<<NBLK, NTHR, SMEM_TOT>>>(xg, Whh0, hhi, (float*)0);

    // Layer 1
    int nw1 = G4 * HID;
    split_fp16_kernel<<<nw1/4/256, 256>>>(Wih1, whi, wlo, nw1);
    hgemm_split_kernel<<<gg, 256>>>(hhi, (const half*)0, whi, wlo, bih1, bhh1, xg, M, HID, 1);
    lstm_layer_mma<<<NBLK, NTHR, SMEM_TOT>>>(xg, Whh1, hhi, lstm_out);

    // Head
    final_linear_kernel<<<BATCH, 128>>>(lstm_out + (size_t)(SEQ-1) * BATCH * HID,
                                        Wlin, blin, ypred);
}